// round 6
// baseline (speedup 1.0000x reference)
#include <cuda_runtime.h>

#define NN    4096
#define BB    256
#define VOC   200
#define TT    128
#define GRID  740
#define THR   128

// ---------------- scratch (device globals; no allocation) ----------------
static __device__ float g_hf[(size_t)NN * BB * 32];      // node states [node][b][feature]
static __device__ float2 g_p2[16 * BB * 16];             // root partials [stride][b][jj]
static __device__ float g_Wl[32 * 32];
static __device__ float g_bl[32];
static __device__ float g_Pa[VOC * 32];
static __device__ float g_Pb[VOC * 32];
static __device__ float g_La[VOC * 32];
static __device__ float g_Lb[VOC * 32];
static __device__ float g_F[BB * 32];
static __device__ float g_Lt[(size_t)BB * TT * 32];
static __device__ float g_v[32];
static __device__ float g_s;
static __device__ int   g_cnt[NN];
static __device__ int   g_cur[NN];
static __device__ int   g_off[NN + 1];
static __device__ int   g_child[NN];
static __device__ int   g_lvcnt[8];
static __device__ int   g_lvnodes[6 * NN];               // lists for heights 0..5
static __device__ int   g_tA[NN * BB];
static __device__ int   g_tB[NN * BB];
static __device__ unsigned g_barctr;

// ---------------- f32x2 helpers ----------------
__device__ __forceinline__ unsigned long long pack2(float lo, float hi) {
    unsigned long long r;
    asm("mov.b64 %0, {%1, %2};" : "=l"(r) : "r"(__float_as_uint(lo)), "r"(__float_as_uint(hi)));
    return r;
}
__device__ __forceinline__ void unpack2(unsigned long long v, float& lo, float& hi) {
    unsigned int a, b;
    asm("mov.b64 {%0, %1}, %2;" : "=r"(a), "=r"(b) : "l"(v));
    lo = __uint_as_float(a);
    hi = __uint_as_float(b);
}
__device__ __forceinline__ void fma2(unsigned long long& d, unsigned long long a, unsigned long long b) {
    asm("fma.rn.f32x2 %0, %1, %2, %0;" : "+l"(d) : "l"(a), "l"(b));
}

// ---------------- global barrier ----------------
__device__ __forceinline__ void gbar(unsigned target) {
    __syncthreads();
    if (threadIdx.x == 0) {
        __threadfence();
        atomicAdd(&g_barctr, 1u);
        unsigned v;
        do {
            asm volatile("ld.acquire.gpu.u32 %0, [%1];" : "=r"(v) : "l"(&g_barctr) : "memory");
        } while (v < target);
    }
    __syncthreads();
}

// ---------------- setup: zero + CSR build + fuse + tables (1 block) ----------------
__global__ void k_setup(const int* parent, const int* height,
                        const float* lw1, const float* lb1, const float* lw2, const float* lb2,
                        const float* fw1, const float* fb1, const float* fw2, const float* fb2,
                        const float* tw, const float* tb,
                        const float* emb, const float* node_w, const float* node_b) {
    __shared__ float u[32];
    __shared__ int sm[1024];
    int t = threadIdx.x;
    // zero
    for (int i = t; i < NN; i += 1024) { g_cnt[i] = 0; g_cur[i] = 0; }
    if (t < 8) g_lvcnt[t] = 0;
    if (t == 0) g_barctr = 0u;
    __syncthreads();
    // CSR count
    for (int c = t; c < NN; c += 1024)
        if (c >= 1) atomicAdd(&g_cnt[parent[c]], 1);
    __syncthreads();
    // scan (1024 threads x 4 elems)
    {
        int c0 = g_cnt[4 * t], c1 = g_cnt[4 * t + 1], c2 = g_cnt[4 * t + 2], c3 = g_cnt[4 * t + 3];
        int s = c0 + c1 + c2 + c3;
        sm[t] = s;
        __syncthreads();
        for (int off = 1; off < 1024; off <<= 1) {
            int v = (t >= off) ? sm[t - off] : 0;
            __syncthreads();
            sm[t] += v;
            __syncthreads();
        }
        int excl = sm[t] - s;
        g_off[4 * t]     = excl;
        g_off[4 * t + 1] = excl + c0;
        g_off[4 * t + 2] = excl + c0 + c1;
        g_off[4 * t + 3] = excl + c0 + c1 + c2;
        if (t == 1023) g_off[NN] = sm[t];
    }
    __syncthreads();
    // fill + level lists
    for (int c = t; c < NN; c += 1024) {
        if (c >= 1) {
            int p = parent[c];
            int pos = atomicAdd(&g_cur[p], 1);
            g_child[g_off[p] + pos] = c;
        }
        int h = height[c];
        if (h < 6) {
            int i = atomicAdd(&g_lvcnt[h], 1);
            g_lvnodes[h * NN + i] = c;
        }
    }
    // fused weights
    int i = t >> 5, j = t & 31;
    float s = 0.f;
    for (int k = 0; k < 32; k++) s += lw1[i * 32 + k] * lw2[k * 32 + j];
    g_Wl[t] = s;
    if (t < 32) {
        float bsum = lb2[t];
        for (int k = 0; k < 32; k++) bsum += lb1[k] * lw2[k * 32 + t];
        g_bl[t] = bsum;
        float uu = 0.f;
        for (int q = 0; q < 32; q++) uu += fw2[t * 32 + q] * tw[q];
        u[t] = uu;
    }
    __syncthreads();
    if (t < 32) {
        float vv = 0.f;
        for (int k = 0; k < 32; k++) vv += fw1[t * 32 + k] * u[k];
        g_v[t] = vv;
    }
    if (t == 0) {
        float ss = tb[0];
        for (int k = 0; k < 32; k++) ss += fb1[k] * u[k];
        for (int q = 0; q < 32; q++) ss += fb2[q] * tw[q];
        g_s = ss;
    }
    __syncthreads();
    // tables
    for (int idx = t; idx < VOC * 32; idx += 1024) {
        int v = idx >> 5, jj = idx & 31;
        float la = g_bl[jj], lb = 0.f, pa = node_b[jj], pb = 0.f;
        for (int e = 0; e < 16; e++) {
            float ev = emb[v * 16 + e];
            la += ev * g_Wl[e * 32 + jj];
            lb += ev * g_Wl[(16 + e) * 32 + jj];
            pa += ev * node_w[e * 32 + jj];
            pb += ev * node_w[(16 + e) * 32 + jj];
        }
        g_La[idx] = la;
        g_Lb[idx] = lb;
        g_Pa[idx] = pa;
        g_Pb[idx] = pb;
    }
}

// ---------------- the mega kernel ----------------
__global__ void __launch_bounds__(THR, 5) k_mega(
    const int* __restrict__ kind,
    const int* __restrict__ tok_a, const int* __restrict__ tok_b,
    const int* __restrict__ ptr_time,
    const float* __restrict__ first_notes, const float* __restrict__ lstm,
    const float* __restrict__ node_w,
    const float* __restrict__ ptr_w, const float* __restrict__ ptr_b,
    float* __restrict__ out)
{
    __shared__ float lssh[32 * 68];
    __shared__ float pwT[32 * 68];
    __shared__ int tileb[32][33];

    const int t = threadIdx.x, bid = blockIdx.x;
    const int wid = t >> 5, lane = t & 31;
    const int jj = lane & 15, half = lane >> 4;
    const int gw = bid * 4 + wid;               // global warp id 0..2959
    const int NW = GRID * 4;

    // W columns in registers: W2[k] = (node_w[32+k][2jj], node_w[32+k][2jj+1])
    unsigned long long W2[32];
    #pragma unroll
    for (int k = 0; k < 32; k++) {
        float2 w = *(const float2*)(node_w + (32 + k) * 32 + 2 * jj);
        W2[k] = pack2(w.x, w.y);
    }

    // matvec + relu for one b (csx/csy spread over 16 lanes) -> float2 result
    auto matvec = [&](float csx, float csy, float px, float py) {
        unsigned long long oA = pack2(px, py);
        unsigned long long oB = pack2(0.f, 0.f);
        #pragma unroll
        for (int kk = 0; kk < 16; kk++) {
            float lo = __shfl_sync(0xffffffffu, csx, kk, 16);
            float hi = __shfl_sync(0xffffffffu, csy, kk, 16);
            fma2(oA, pack2(lo, lo), W2[2 * kk]);
            fma2(oB, pack2(hi, hi), W2[2 * kk + 1]);
        }
        float a0, a1, b0f, b1f;
        unpack2(oA, a0, a1);
        unpack2(oB, b0f, b1f);
        return make_float2(fmaxf(a0 + b0f, 0.f), fmaxf(a1 + b1f, 0.f));
    };

    // ================= Phase A: transpose | Lt | F =================
    if (bid < 512) {
        for (int ti = bid; ti < 2048; ti += 512) {
            int arr = ti >> 10;
            int tile = ti & 1023;
            int pt = tile >> 3, bt = tile & 7;
            const int* src = arr ? tok_b : tok_a;
            int* dst = arr ? g_tB : g_tA;
            for (int r = wid; r < 32; r += 4)
                tileb[r][lane] = src[(size_t)(bt * 32 + r) * NN + pt * 32 + lane];
            __syncthreads();
            for (int r = wid; r < 32; r += 4)
                dst[(size_t)(pt * 32 + r) * BB + bt * 32 + lane] = tileb[lane][r];
            __syncthreads();
        }
    } else if (bid < 704) {
        for (int i = t; i < 2048; i += THR)
            pwT[(i & 31) * 68 + (i >> 5)] = ptr_w[2048 + i];
        for (int g = bid - 512; g < 1024; g += 192) {
            __syncthreads();
            size_t base = (size_t)g * 32 * 64;
            for (int i = t; i < 2048; i += THR)
                lssh[(i >> 6) * 68 + (i & 63)] = lstm[base + i];
            __syncthreads();
            float sacc[8];
            #pragma unroll
            for (int r = 0; r < 8; r++) sacc[r] = 0.f;
            #pragma unroll
            for (int k4 = 0; k4 < 64; k4 += 4) {
                float4 wv = *(const float4*)(pwT + lane * 68 + k4);
                #pragma unroll
                for (int r = 0; r < 8; r++) {
                    float4 lv = *(const float4*)(lssh + (wid * 8 + r) * 68 + k4);
                    sacc[r] += lv.x * wv.x + lv.y * wv.y + lv.z * wv.z + lv.w * wv.w;
                }
            }
            int row0 = g * 32 + wid * 8;
            #pragma unroll
            for (int r = 0; r < 8; r++)
                g_Lt[(size_t)(row0 + r) * 32 + lane] = sacc[r];
        }
    } else {
        for (int idx = (bid - 704) * THR + t; idx < BB * 32; idx += 36 * THR) {
            int b = idx >> 5, j = idx & 31;
            float s = ptr_b[j];
            for (int k = 0; k < 64; k++) s += first_notes[b * 64 + k] * ptr_w[k * 32 + j];
            g_F[idx] = s;
        }
    }
    gbar(GRID * 1);

    // ================= Phase B: leaf (full batch, warp per node-quarter) ========
    {
        int cnt = g_lvcnt[0];
        int nunits = cnt * 4;
        for (int u = gw; u < nunits; u += NW) {
            int node = g_lvnodes[u >> 2];
            int q = u & 3;
            int kd = kind[node];
            int tbase = node * BB;
            if (kd == 0) {
                #pragma unroll 2
                for (int bp = q * 32; bp < q * 32 + 32; bp++) {
                    int b = bp * 2 + half;
                    int ta = g_tA[tbase + b], tb = g_tB[tbase + b];
                    float2 x = *(const float2*)(g_La + ta * 32 + 2 * jj);
                    float2 y = *(const float2*)(g_Lb + tb * 32 + 2 * jj);
                    *(float2*)(g_hf + ((size_t)node * BB + b) * 32 + 2 * jj) =
                        make_float2(x.x + y.x, x.y + y.y);
                }
            } else {
                #pragma unroll 2
                for (int bp = q * 32; bp < q * 32 + 32; bp++) {
                    int b = bp * 2 + half;
                    int tm = ptr_time[(size_t)b * NN + node];
                    float2 x = *(const float2*)(g_F + b * 32 + 2 * jj);
                    float2 y = *(const float2*)(g_Lt + ((size_t)b * TT + tm) * 32 + 2 * jj);
                    *(float2*)(g_hf + ((size_t)node * BB + b) * 32 + 2 * jj) =
                        make_float2(x.x + y.x, x.y + y.y);
                }
            }
        }
    }
    gbar(GRID * 2);

    // ================= Levels 1..5 =================
    for (int lvl = 1; lvl <= 5; lvl++) {
        int cnt = g_lvcnt[lvl];
        int nunits = cnt * 4;
        const int* list = g_lvnodes + lvl * NN;
        for (int u = gw; u < nunits; u += NW) {
            int node = list[u >> 2];
            int q = u & 3;
            int c0 = g_off[node], c1 = g_off[node + 1];
            int chl[4];
            #pragma unroll
            for (int k = 0; k < 4; k++) chl[k] = (c0 + k < c1) ? g_child[c0 + k] : -1;
            int tbase = node * BB;
            #pragma unroll 2
            for (int bp = q * 32; bp < q * 32 + 32; bp++) {
                int b = bp * 2 + half;
                float csx = 0.f, csy = 0.f;
                #pragma unroll
                for (int k = 0; k < 4; k++) {
                    int c = chl[k];
                    if (c >= 0) {
                        float2 v = *(const float2*)(g_hf + ((size_t)c * BB + b) * 32 + 2 * jj);
                        csx += v.x; csy += v.y;
                    }
                }
                for (int ci = c0 + 4; ci < c1; ci++) {
                    int c = g_child[ci];
                    float2 v = *(const float2*)(g_hf + ((size_t)c * BB + b) * 32 + 2 * jj);
                    csx += v.x; csy += v.y;
                }
                int ta = g_tA[tbase + b], tb = g_tB[tbase + b];
                float2 pa = *(const float2*)(g_Pa + ta * 32 + 2 * jj);
                float2 pb = *(const float2*)(g_Pb + tb * 32 + 2 * jj);
                float2 r = matvec(csx, csy, pa.x + pb.x, pa.y + pb.y);
                *(float2*)(g_hf + ((size_t)node * BB + b) * 32 + 2 * jj) = r;
            }
        }
        gbar(GRID * (2 + lvl));
    }

    // ================= F1: root partial sums (512 blocks, 16 strides) ==========
    if (bid < 512) {
        int u = gw;                       // 0..2047
        int bp = u & 127, stride = u >> 7;
        int b = bp * 2 + half;
        float csx = 0.f, csy = 0.f;
        int c0 = g_off[0], c1 = g_off[1];
        for (int ci = c0 + stride; ci < c1; ci += 16) {
            int c = g_child[ci];
            float2 v = *(const float2*)(g_hf + ((size_t)c * BB + b) * 32 + 2 * jj);
            csx += v.x; csy += v.y;
        }
        g_p2[(stride * BB + b) * 16 + jj] = make_float2(csx, csy);
    }
    gbar(GRID * 8);

    // ================= F23: finish (32 blocks) =================
    if (bid < 32) {
        int bp = bid * 4 + wid;           // 0..127
        int b = bp * 2 + half;
        float csx = 0.f, csy = 0.f;
        #pragma unroll
        for (int q = 0; q < 16; q++) {
            float2 p = g_p2[(q * BB + b) * 16 + jj];
            csx += p.x; csy += p.y;
        }
        int ta = g_tA[b];
        int tb = g_tB[b];
        float2 pa = *(const float2*)(g_Pa + ta * 32 + 2 * jj);
        float2 pb = *(const float2*)(g_Pb + tb * 32 + 2 * jj);
        float2 r = matvec(csx, csy, pa.x + pb.x, pa.y + pb.y);
        float2 v2 = *(const float2*)(g_v + 2 * jj);
        float d = r.x * v2.x + r.y * v2.y;
        #pragma unroll
        for (int off = 8; off; off >>= 1) d += __shfl_xor_sync(0xffffffffu, d, off, 16);
        if (jj == 0) out[b] = d + g_s;
    }
}

// ---------------- launch ----------------
extern "C" void kernel_launch(void* const* d_in, const int* in_sizes, int n_in,
                              void* d_out, int out_size) {
    const int*   kind        = (const int*)d_in[0];
    const int*   height      = (const int*)d_in[1];
    const int*   parent      = (const int*)d_in[2];
    const int*   tok_a       = (const int*)d_in[3];
    const int*   tok_b       = (const int*)d_in[4];
    const int*   ptr_time    = (const int*)d_in[5];
    const float* first_notes = (const float*)d_in[6];
    const float* lstm_out    = (const float*)d_in[7];
    const float* embedding   = (const float*)d_in[8];
    const float* leaf_w1     = (const float*)d_in[9];
    const float* leaf_b1     = (const float*)d_in[10];
    const float* leaf_w2     = (const float*)d_in[11];
    const float* leaf_b2     = (const float*)d_in[12];
    const float* node_w      = (const float*)d_in[13];
    const float* node_b      = (const float*)d_in[14];
    const float* ptr_w       = (const float*)d_in[15];
    const float* ptr_b       = (const float*)d_in[16];
    const float* ff_w1       = (const float*)d_in[17];
    const float* ff_b1       = (const float*)d_in[18];
    const float* ff_w2       = (const float*)d_in[19];
    const float* ff_b2       = (const float*)d_in[20];
    const float* tail_w      = (const float*)d_in[21];
    const float* tail_b      = (const float*)d_in[22];
    float* out = (float*)d_out;

    k_setup<<<1, 1024>>>(parent, height,
                         leaf_w1, leaf_b1, leaf_w2, leaf_b2,
                         ff_w1, ff_b1, ff_w2, ff_b2, tail_w, tail_b,
                         embedding, node_w, node_b);
    k_mega<<<GRID, THR>>>(kind, tok_a, tok_b, ptr_time,
                          first_notes, lstm_out, node_w, ptr_w, ptr_b, out);
}

// round 7
// speedup vs baseline: 1.3227x; 1.3227x over previous
#include <cuda_runtime.h>

#define NN    4096
#define BB    256
#define VOC   200
#define TT    128
#define LVGRID 296

// ---------------- scratch (device globals; no allocation) ----------------
static __device__ float4 g_h4[(size_t)NN * 8 * BB];      // node states [node][q][b]
static __device__ float4 g_p4[64 * 8 * BB];              // root partials [s][q][b]
static __device__ float g_Wl[32 * 32];
static __device__ float g_bl[32];
static __device__ float g_Pa[VOC * 32];
static __device__ float g_Pb[VOC * 32];
static __device__ float g_La[VOC * 32];
static __device__ float g_Lb[VOC * 32];
static __device__ float g_F[BB * 32];
static __device__ float g_Lt[(size_t)BB * TT * 32];
static __device__ float g_v[32];
static __device__ float g_s;
static __device__ int   g_cnt[NN];
static __device__ int   g_cur[NN];
static __device__ int   g_off[NN + 1];
static __device__ int   g_child[NN];
static __device__ int   g_lvcnt[8];
static __device__ int   g_lvnodes[6 * NN];
static __device__ int   g_tA[NN * BB];
static __device__ int   g_tB[NN * BB];

// ---------------- f32x2 helpers ----------------
__device__ __forceinline__ unsigned long long pack2(float lo, float hi) {
    unsigned long long r;
    asm("mov.b64 %0, {%1, %2};" : "=l"(r) : "r"(__float_as_uint(lo)), "r"(__float_as_uint(hi)));
    return r;
}
__device__ __forceinline__ void unpack2(unsigned long long v, float& lo, float& hi) {
    unsigned int a, b;
    asm("mov.b64 {%0, %1}, %2;" : "=r"(a), "=r"(b) : "l"(v));
    lo = __uint_as_float(a);
    hi = __uint_as_float(b);
}
__device__ __forceinline__ void fma2(unsigned long long& d, unsigned long long a, unsigned long long b) {
    asm("fma.rn.f32x2 %0, %1, %2, %0;" : "+l"(d) : "l"(a), "l"(b));
}

// ---------------- token transpose [b][p] -> [p][b] ----------------
__global__ void k_tr(const int* __restrict__ a, const int* __restrict__ b) {
    __shared__ int tile[32][33];
    const int* src = blockIdx.z == 0 ? a : b;
    int* dst = blockIdx.z == 0 ? g_tA : g_tB;
    int p0 = blockIdx.x * 32, b0 = blockIdx.y * 32;
    tile[threadIdx.y][threadIdx.x] = src[(size_t)(b0 + threadIdx.y) * NN + p0 + threadIdx.x];
    __syncthreads();
    dst[(size_t)(p0 + threadIdx.y) * BB + b0 + threadIdx.x] = tile[threadIdx.x][threadIdx.y];
}

// ---------------- Lt: [B*T,64] @ [64,32], 1 thread per output ----------------
__global__ void __launch_bounds__(256) k_lt(const float* __restrict__ lstm,
                                            const float* __restrict__ pw) {
    int gid = blockIdx.x * 256 + threadIdx.x;     // 0 .. 1M-1
    int r = gid >> 5, j = gid & 31;
    const float* lr = lstm + (size_t)r * 64;
    float s = 0.f;
    #pragma unroll
    for (int k = 0; k < 64; k++)
        s += __ldg(lr + k) * __ldg(pw + (64 + k) * 32 + j);
    g_Lt[(size_t)r * 32 + j] = s;
}

// ---------------- setup: zero + CSR + fuse + tables + F (1 block) ----------------
__global__ void k_setup(const int* parent, const int* height,
                        const float* lw1, const float* lb1, const float* lw2, const float* lb2,
                        const float* fw1, const float* fb1, const float* fw2, const float* fb2,
                        const float* tw, const float* tb,
                        const float* emb, const float* node_w, const float* node_b,
                        const float* fn, const float* pw, const float* pbias) {
    __shared__ float u[32];
    __shared__ int sm[1024];
    int t = threadIdx.x;
    for (int i = t; i < NN; i += 1024) { g_cnt[i] = 0; g_cur[i] = 0; }
    if (t < 8) g_lvcnt[t] = 0;
    __syncthreads();
    for (int c = t; c < NN; c += 1024)
        if (c >= 1) atomicAdd(&g_cnt[parent[c]], 1);
    __syncthreads();
    {
        int c0 = g_cnt[4 * t], c1 = g_cnt[4 * t + 1], c2 = g_cnt[4 * t + 2], c3 = g_cnt[4 * t + 3];
        int s = c0 + c1 + c2 + c3;
        sm[t] = s;
        __syncthreads();
        for (int off = 1; off < 1024; off <<= 1) {
            int v = (t >= off) ? sm[t - off] : 0;
            __syncthreads();
            sm[t] += v;
            __syncthreads();
        }
        int excl = sm[t] - s;
        g_off[4 * t]     = excl;
        g_off[4 * t + 1] = excl + c0;
        g_off[4 * t + 2] = excl + c0 + c1;
        g_off[4 * t + 3] = excl + c0 + c1 + c2;
        if (t == 1023) g_off[NN] = sm[t];
    }
    __syncthreads();
    for (int c = t; c < NN; c += 1024) {
        if (c >= 1) {
            int p = parent[c];
            int pos = atomicAdd(&g_cur[p], 1);
            g_child[g_off[p] + pos] = c;
        }
        int h = height[c];
        if (h < 6) {
            int i = atomicAdd(&g_lvcnt[h], 1);
            g_lvnodes[h * NN + i] = c;
        }
    }
    // fused leaf weights + readout vector
    int i = t >> 5, j = t & 31;
    float s = 0.f;
    for (int k = 0; k < 32; k++) s += lw1[i * 32 + k] * lw2[k * 32 + j];
    g_Wl[t] = s;
    if (t < 32) {
        float bsum = lb2[t];
        for (int k = 0; k < 32; k++) bsum += lb1[k] * lw2[k * 32 + t];
        g_bl[t] = bsum;
        float uu = 0.f;
        for (int q = 0; q < 32; q++) uu += fw2[t * 32 + q] * tw[q];
        u[t] = uu;
    }
    __syncthreads();
    if (t < 32) {
        float vv = 0.f;
        for (int k = 0; k < 32; k++) vv += fw1[t * 32 + k] * u[k];
        g_v[t] = vv;
    }
    if (t == 0) {
        float ss = tb[0];
        for (int k = 0; k < 32; k++) ss += fb1[k] * u[k];
        for (int q = 0; q < 32; q++) ss += fb2[q] * tw[q];
        g_s = ss;
    }
    __syncthreads();
    // tables
    for (int idx = t; idx < VOC * 32; idx += 1024) {
        int v = idx >> 5, jj = idx & 31;
        float la = g_bl[jj], lb = 0.f, pa = node_b[jj], pb = 0.f;
        for (int e = 0; e < 16; e++) {
            float ev = emb[v * 16 + e];
            la += ev * g_Wl[e * 32 + jj];
            lb += ev * g_Wl[(16 + e) * 32 + jj];
            pa += ev * node_w[e * 32 + jj];
            pb += ev * node_w[(16 + e) * 32 + jj];
        }
        g_La[idx] = la;
        g_Lb[idx] = lb;
        g_Pa[idx] = pa;
        g_Pb[idx] = pb;
    }
    // F = first_notes @ ptr_w_top + ptr_b
    for (int idx = t; idx < BB * 32; idx += 1024) {
        int b = idx >> 5, jj = idx & 31;
        float sf = pbias[jj];
        for (int k = 0; k < 64; k++) sf += fn[b * 64 + k] * pw[k * 32 + jj];
        g_F[idx] = sf;
    }
}

// ---------------- leaf init (height 0) ----------------
__global__ void __launch_bounds__(256, 2) k_init(const int* __restrict__ kind,
                                                 const int* __restrict__ ptr_time) {
    extern __shared__ float dsm[];
    float* Las = dsm;            // 200*36
    float* Lbs = dsm + 7200;
    int t = threadIdx.x;
    int cnt = g_lvcnt[0];
    if ((int)blockIdx.x >= cnt) return;
    for (int i = t; i < VOC * 32; i += 256) {
        int v = i >> 5, j = i & 31;
        Las[v * 36 + j] = g_La[i];
        Lbs[v * 36 + j] = g_Lb[i];
    }
    __syncthreads();
    int b = t;
    for (int ni = blockIdx.x; ni < cnt; ni += gridDim.x) {
        int node = g_lvnodes[ni];
        int kd = kind[node];
        float4 r[8];
        if (kd == 0) {
            int ta = g_tA[node * BB + b];
            int tb = g_tB[node * BB + b];
            const float4* A  = (const float4*)(Las + ta * 36);
            const float4* Bv = (const float4*)(Lbs + tb * 36);
            #pragma unroll
            for (int q = 0; q < 8; q++) {
                float4 x = A[q], y = Bv[q];
                r[q] = make_float4(x.x + y.x, x.y + y.y, x.z + y.z, x.w + y.w);
            }
        } else {
            int tm = ptr_time[(size_t)b * NN + node];
            const float4* A  = (const float4*)(g_F + b * 32);
            const float4* Bv = (const float4*)(g_Lt + ((size_t)b * TT + tm) * 32);
            #pragma unroll
            for (int q = 0; q < 8; q++) {
                float4 x = A[q], y = Bv[q];
                r[q] = make_float4(x.x + y.x, x.y + y.y, x.z + y.z, x.w + y.w);
            }
        }
        float4* dst = g_h4 + (size_t)node * 2048 + b;
        #pragma unroll
        for (int q = 0; q < 8; q++) dst[q * 256] = r[q];
    }
}

// ---------------- level update (heights 1..5) ----------------
__global__ void __launch_bounds__(256, 2) k_level(const float* __restrict__ node_w, int lvl) {
    extern __shared__ float dsm[];
    float* Pas = dsm;                               // 200*36
    float* Pbs = dsm + 7200;                        // 200*36
    unsigned long long* Wsh = (unsigned long long*)(dsm + 14400);  // 512 u64 = 4KB
    int t = threadIdx.x;
    int cnt = g_lvcnt[lvl];
    if ((int)blockIdx.x >= cnt) return;
    for (int i = t; i < VOC * 32; i += 256) {
        int v = i >> 5, j = i & 31;
        Pas[v * 36 + j] = g_Pa[i];
        Pbs[v * 36 + j] = g_Pb[i];
    }
    {
        const ulonglong2* wsrc = (const ulonglong2*)(node_w + 1024);
        ((ulonglong2*)Wsh)[t] = wsrc[t];            // 256 x 16B = bottom half of node_w
    }
    __syncthreads();
    const int* list = g_lvnodes + lvl * NN;
    int b = t;
    for (int ni = blockIdx.x; ni < cnt; ni += gridDim.x) {
        int node = list[ni];
        int c0 = g_off[node], c1 = g_off[node + 1];
        float4 a[8];
        #pragma unroll
        for (int q = 0; q < 8; q++) a[q] = make_float4(0.f, 0.f, 0.f, 0.f);
        for (int ci = c0; ci < c1; ci++) {
            int c = g_child[ci];
            const float4* src = g_h4 + (size_t)c * 2048 + b;
            #pragma unroll
            for (int q = 0; q < 8; q++) {
                float4 v = src[q * 256];
                a[q].x += v.x; a[q].y += v.y; a[q].z += v.z; a[q].w += v.w;
            }
        }
        int ta = g_tA[node * BB + b];
        int tb = g_tB[node * BB + b];
        const float4* pa = (const float4*)(Pas + ta * 36);
        const float4* pb = (const float4*)(Pbs + tb * 36);
        unsigned long long o2[16];
        #pragma unroll
        for (int q = 0; q < 8; q++) {
            float4 x = pa[q], y = pb[q];
            o2[2 * q]     = pack2(x.x + y.x, x.y + y.y);
            o2[2 * q + 1] = pack2(x.z + y.z, x.w + y.w);
        }
        const float* af = (const float*)a;
        #pragma unroll
        for (int k = 0; k < 32; k++) {
            unsigned long long a2 = pack2(af[k], af[k]);
            const ulonglong2* wrow = (const ulonglong2*)(Wsh + k * 16);
            #pragma unroll
            for (int j2 = 0; j2 < 8; j2++) {
                ulonglong2 w = wrow[j2];
                fma2(o2[2 * j2], a2, w.x);
                fma2(o2[2 * j2 + 1], a2, w.y);
            }
        }
        float4* dst = g_h4 + (size_t)node * 2048 + b;
        #pragma unroll
        for (int q = 0; q < 8; q++) {
            float l0, h0, l1, h1;
            unpack2(o2[2 * q], l0, h0);
            unpack2(o2[2 * q + 1], l1, h1);
            dst[q * 256] = make_float4(fmaxf(l0, 0.f), fmaxf(h0, 0.f),
                                       fmaxf(l1, 0.f), fmaxf(h1, 0.f));
        }
    }
}

// ---------------- root partial sums (64 blocks) ----------------
__global__ void __launch_bounds__(256) k_f1() {
    int b = threadIdx.x, s = blockIdx.x;
    float4 acc[8];
    #pragma unroll
    for (int q = 0; q < 8; q++) acc[q] = make_float4(0.f, 0.f, 0.f, 0.f);
    int c0 = g_off[0], c1 = g_off[1];
    for (int ci = c0 + s; ci < c1; ci += 64) {
        int c = g_child[ci];
        const float4* src = g_h4 + (size_t)c * 2048 + b;
        #pragma unroll
        for (int q = 0; q < 8; q++) {
            float4 v = src[q * 256];
            acc[q].x += v.x; acc[q].y += v.y; acc[q].z += v.z; acc[q].w += v.w;
        }
    }
    float4* dst = g_p4 + (size_t)s * 2048 + b;
    #pragma unroll
    for (int q = 0; q < 8; q++) dst[q * 256] = acc[q];
}

// ---------------- root finish (1 block) ----------------
__global__ void __launch_bounds__(256) k_f23(const float* __restrict__ node_w,
                                             float* __restrict__ out) {
    int b = threadIdx.x;
    float4 acc[8];
    #pragma unroll
    for (int q = 0; q < 8; q++) acc[q] = make_float4(0.f, 0.f, 0.f, 0.f);
    for (int s = 0; s < 64; s++) {
        const float4* src = g_p4 + (size_t)s * 2048 + b;
        #pragma unroll
        for (int q = 0; q < 8; q++) {
            float4 v = src[q * 256];
            acc[q].x += v.x; acc[q].y += v.y; acc[q].z += v.z; acc[q].w += v.w;
        }
    }
    int ta = g_tA[b];
    int tb = g_tB[b];
    unsigned long long o2[16];
    #pragma unroll
    for (int q = 0; q < 8; q++) {
        float4 x = *(const float4*)(g_Pa + ta * 32 + 4 * q);
        float4 y = *(const float4*)(g_Pb + tb * 32 + 4 * q);
        o2[2 * q]     = pack2(x.x + y.x, x.y + y.y);
        o2[2 * q + 1] = pack2(x.z + y.z, x.w + y.w);
    }
    const float* af = (const float*)acc;
    #pragma unroll
    for (int k = 0; k < 32; k++) {
        unsigned long long a2 = pack2(af[k], af[k]);
        const ulonglong2* wrow = (const ulonglong2*)(node_w + 1024 + k * 32);
        #pragma unroll
        for (int j2 = 0; j2 < 8; j2++) {
            ulonglong2 w = wrow[j2];
            fma2(o2[2 * j2], a2, w.x);
            fma2(o2[2 * j2 + 1], a2, w.y);
        }
    }
    float val = 0.f;
    #pragma unroll
    for (int q = 0; q < 8; q++) {
        float l0, h0, l1, h1;
        unpack2(o2[2 * q], l0, h0);
        unpack2(o2[2 * q + 1], l1, h1);
        val += fmaxf(l0, 0.f) * g_v[4 * q]     + fmaxf(h0, 0.f) * g_v[4 * q + 1]
             + fmaxf(l1, 0.f) * g_v[4 * q + 2] + fmaxf(h1, 0.f) * g_v[4 * q + 3];
    }
    out[b] = val + g_s;
}

// ---------------- launch ----------------
extern "C" void kernel_launch(void* const* d_in, const int* in_sizes, int n_in,
                              void* d_out, int out_size) {
    const int*   kind        = (const int*)d_in[0];
    const int*   height      = (const int*)d_in[1];
    const int*   parent      = (const int*)d_in[2];
    const int*   tok_a       = (const int*)d_in[3];
    const int*   tok_b       = (const int*)d_in[4];
    const int*   ptr_time    = (const int*)d_in[5];
    const float* first_notes = (const float*)d_in[6];
    const float* lstm_out    = (const float*)d_in[7];
    const float* embedding   = (const float*)d_in[8];
    const float* leaf_w1     = (const float*)d_in[9];
    const float* leaf_b1     = (const float*)d_in[10];
    const float* leaf_w2     = (const float*)d_in[11];
    const float* leaf_b2     = (const float*)d_in[12];
    const float* node_w      = (const float*)d_in[13];
    const float* node_b      = (const float*)d_in[14];
    const float* ptr_w       = (const float*)d_in[15];
    const float* ptr_b       = (const float*)d_in[16];
    const float* ff_w1       = (const float*)d_in[17];
    const float* ff_b1       = (const float*)d_in[18];
    const float* ff_w2       = (const float*)d_in[19];
    const float* ff_b2       = (const float*)d_in[20];
    const float* tail_w      = (const float*)d_in[21];
    const float* tail_b      = (const float*)d_in[22];
    float* out = (float*)d_out;

    static int attr_done = 0;
    if (!attr_done) {
        cudaFuncSetAttribute(k_init,  cudaFuncAttributeMaxDynamicSharedMemorySize, 57600);
        cudaFuncSetAttribute(k_level, cudaFuncAttributeMaxDynamicSharedMemorySize, 61696);
        attr_done = 1;
    }

    k_tr<<<dim3(NN / 32, BB / 32, 2), dim3(32, 32)>>>(tok_a, tok_b);
    k_lt<<<BB * TT * 32 / 256, 256>>>(lstm_out, ptr_w);
    k_setup<<<1, 1024>>>(parent, height,
                         leaf_w1, leaf_b1, leaf_w2, leaf_b2,
                         ff_w1, ff_b1, ff_w2, ff_b2, tail_w, tail_b,
                         embedding, node_w, node_b,
                         first_notes, ptr_w, ptr_b);
    k_init<<<LVGRID, 256, 57600>>>(kind, ptr_time);
    for (int lvl = 1; lvl <= 5; lvl++)
        k_level<<<LVGRID, 256, 61696>>>(node_w, lvl);
    k_f1<<<64, 256>>>();
    k_f23<<<1, 256>>>(node_w, out);
}

// round 8
// speedup vs baseline: 1.3520x; 1.0222x over previous
#include <cuda_runtime.h>

#define NN    4096
#define BB    256
#define VOC   200
#define TT    128
#define LVG   740

// ---------------- scratch (device globals; no allocation) ----------------
static __device__ float4 g_h4[(size_t)NN * 8 * BB];      // [node][q][b]
static __device__ float4 g_p4[64 * 8 * BB];              // root partials
static __device__ float g_Wl[32 * 32];
static __device__ float g_bl[32];
static __device__ float g_Pa[VOC * 32];
static __device__ float g_Pb[VOC * 32];
static __device__ float g_La[VOC * 32];
static __device__ float g_Lb[VOC * 32];
static __device__ float g_F[BB * 32];
static __device__ float g_Lt[(size_t)BB * TT * 32];
static __device__ float g_v[32];
static __device__ float g_s;
static __device__ int   g_cnt[NN];
static __device__ int   g_cur[NN];
static __device__ int   g_off[NN + 1];
static __device__ int   g_child[NN];
static __device__ int   g_lvcnt[8];
static __device__ int   g_lvnodes[6 * NN];
static __device__ int   g_tA[NN * BB];
static __device__ int   g_tB[NN * BB];

// ---------------- f32x2 helpers ----------------
__device__ __forceinline__ unsigned long long pack2(float lo, float hi) {
    unsigned long long r;
    asm("mov.b64 %0, {%1, %2};" : "=l"(r) : "r"(__float_as_uint(lo)), "r"(__float_as_uint(hi)));
    return r;
}
__device__ __forceinline__ void unpack2(unsigned long long v, float& lo, float& hi) {
    unsigned int a, b;
    asm("mov.b64 {%0, %1}, %2;" : "=r"(a), "=r"(b) : "l"(v));
    lo = __uint_as_float(a);
    hi = __uint_as_float(b);
}
__device__ __forceinline__ void fma2(unsigned long long& d, unsigned long long a, unsigned long long b) {
    asm("fma.rn.f32x2 %0, %1, %2, %0;" : "+l"(d) : "l"(a), "l"(b));
}
__device__ __forceinline__ unsigned long long add2(unsigned long long a, unsigned long long b) {
    unsigned long long r;
    asm("add.rn.f32x2 %0, %1, %2;" : "=l"(r) : "l"(a), "l"(b));
    return r;
}

// ============ prep: transpose | Lt+F | CSR/scan/fuse/tables (role split) ============
__global__ void __launch_bounds__(256) k_prep(
    const int* __restrict__ parent, const int* __restrict__ height,
    const int* __restrict__ tok_a, const int* __restrict__ tok_b,
    const float* __restrict__ lstm, const float* __restrict__ fn,
    const float* __restrict__ pw, const float* __restrict__ pbias,
    const float* __restrict__ lw1, const float* __restrict__ lb1,
    const float* __restrict__ lw2, const float* __restrict__ lb2,
    const float* __restrict__ fw1, const float* __restrict__ fb1,
    const float* __restrict__ fw2, const float* __restrict__ fb2,
    const float* __restrict__ tw, const float* __restrict__ tb,
    const float* __restrict__ emb, const float* __restrict__ node_w,
    const float* __restrict__ node_b)
{
    int bid = blockIdx.x, t = threadIdx.x;
    if (bid < 2048) {
        // token transpose: 1024 tiles of 32x32 per array
        __shared__ int tile[32][33];
        int arr = bid >> 10, tl = bid & 1023;
        int pt = tl >> 3, bt = tl & 7;
        const int* src = arr ? tok_b : tok_a;
        int* dst = arr ? g_tB : g_tA;
        int x = t & 31, y0 = t >> 5;
        #pragma unroll
        for (int y = y0; y < 32; y += 8)
            tile[y][x] = src[(size_t)(bt * 32 + y) * NN + pt * 32 + x];
        __syncthreads();
        #pragma unroll
        for (int y = y0; y < 32; y += 8)
            dst[(size_t)(pt * 32 + y) * BB + bt * 32 + x] = tile[x][y];
    } else if (bid < 6176) {
        // Lt (rows 0..32767) and F (rows 32768..33023): 1 thread per output
        int gid = (bid - 2048) * 256 + t;
        int r = gid >> 5, j = gid & 31;
        if (r < BB * TT) {
            const float* lr = lstm + (size_t)r * 64;
            float s = 0.f;
            #pragma unroll
            for (int k = 0; k < 64; k++)
                s += __ldg(lr + k) * __ldg(pw + (64 + k) * 32 + j);
            g_Lt[(size_t)r * 32 + j] = s;
        } else {
            int b = r - BB * TT;
            float s = pbias[j];
            #pragma unroll
            for (int k = 0; k < 64; k++)
                s += __ldg(fn + b * 64 + k) * __ldg(pw + k * 32 + j);
            g_F[b * 32 + j] = s;
        }
    } else {
        // serial setup block
        __shared__ int sc[256];
        __shared__ float u[32];
        for (int i = t; i < NN; i += 256) { g_cnt[i] = 0; g_cur[i] = 0; }
        if (t < 8) g_lvcnt[t] = 0;
        __syncthreads();
        for (int c = t; c < NN; c += 256)
            if (c >= 1) atomicAdd(&g_cnt[parent[c]], 1);
        __syncthreads();
        int base = t * 16;
        int loc[16];
        int run = 0;
        #pragma unroll
        for (int r = 0; r < 16; r++) { loc[r] = run; run += g_cnt[base + r]; }
        sc[t] = run;
        __syncthreads();
        for (int off = 1; off < 256; off <<= 1) {
            int v = (t >= off) ? sc[t - off] : 0;
            __syncthreads();
            sc[t] += v;
            __syncthreads();
        }
        int excl = sc[t] - run;
        #pragma unroll
        for (int r = 0; r < 16; r++) g_off[base + r] = excl + loc[r];
        if (t == 255) g_off[NN] = sc[255];
        __syncthreads();
        for (int c = t; c < NN; c += 256) {
            if (c >= 1) {
                int p = parent[c];
                int pos = atomicAdd(&g_cur[p], 1);
                g_child[g_off[p] + pos] = c;
            }
            int h = height[c];
            if (h < 6) {
                int i = atomicAdd(&g_lvcnt[h], 1);
                g_lvnodes[h * NN + i] = c;
            }
        }
        // fused leaf weights
        for (int idx = t; idx < 1024; idx += 256) {
            int i = idx >> 5, j = idx & 31;
            float s = 0.f;
            for (int k = 0; k < 32; k++) s += lw1[i * 32 + k] * lw2[k * 32 + j];
            g_Wl[idx] = s;
        }
        if (t < 32) {
            float bsum = lb2[t];
            for (int k = 0; k < 32; k++) bsum += lb1[k] * lw2[k * 32 + t];
            g_bl[t] = bsum;
            float uu = 0.f;
            for (int q = 0; q < 32; q++) uu += fw2[t * 32 + q] * tw[q];
            u[t] = uu;
        }
        __syncthreads();
        if (t < 32) {
            float vv = 0.f;
            for (int k = 0; k < 32; k++) vv += fw1[t * 32 + k] * u[k];
            g_v[t] = vv;
        }
        if (t == 0) {
            float ss = tb[0];
            for (int k = 0; k < 32; k++) ss += fb1[k] * u[k];
            for (int q = 0; q < 32; q++) ss += fb2[q] * tw[q];
            g_s = ss;
        }
        __syncthreads();
        for (int idx = t; idx < VOC * 32; idx += 256) {
            int v = idx >> 5, jj = idx & 31;
            float la = g_bl[jj], lb = 0.f, pa = node_b[jj], pb = 0.f;
            for (int e = 0; e < 16; e++) {
                float ev = emb[v * 16 + e];
                la += ev * g_Wl[e * 32 + jj];
                lb += ev * g_Wl[(16 + e) * 32 + jj];
                pa += ev * node_w[e * 32 + jj];
                pb += ev * node_w[(16 + e) * 32 + jj];
            }
            g_La[idx] = la;
            g_Lb[idx] = lb;
            g_Pa[idx] = pa;
            g_Pb[idx] = pb;
        }
    }
}

// ============ leaf init: one node per block, global-L1 table gathers ============
__global__ void __launch_bounds__(256, 6) k_init(const int* __restrict__ kind,
                                                 const int* __restrict__ ptr_time) {
    int cnt = g_lvcnt[0];
    int b = threadIdx.x;
    for (int ni = blockIdx.x; ni < cnt; ni += gridDim.x) {
        int node = g_lvnodes[ni];
        int kd = kind[node];
        float4 r[8];
        if (kd == 0) {
            int ta = g_tA[node * BB + b];
            int tb = g_tB[node * BB + b];
            const float4* A  = (const float4*)(g_La + ta * 32);
            const float4* Bv = (const float4*)(g_Lb + tb * 32);
            #pragma unroll
            for (int q = 0; q < 8; q++) {
                float4 x = A[q], y = Bv[q];
                r[q] = make_float4(x.x + y.x, x.y + y.y, x.z + y.z, x.w + y.w);
            }
        } else {
            int tm = ptr_time[(size_t)b * NN + node];
            const float4* A  = (const float4*)(g_F + b * 32);
            const float4* Bv = (const float4*)(g_Lt + ((size_t)b * TT + tm) * 32);
            #pragma unroll
            for (int q = 0; q < 8; q++) {
                float4 x = A[q], y = Bv[q];
                r[q] = make_float4(x.x + y.x, x.y + y.y, x.z + y.z, x.w + y.w);
            }
        }
        float4* dst = g_h4 + (size_t)node * 2048 + b;
        #pragma unroll
        for (int q = 0; q < 8; q++) dst[q * 256] = r[q];
    }
}

// ============ level: one node per block, smem-staged csum, 4 blocks/SM ============
__global__ void __launch_bounds__(256, 4) k_level(const float* __restrict__ node_w, int lvl) {
    __shared__ __align__(16) unsigned long long Wsh[512];   // 4KB: bottom half of node_w
    __shared__ float csum[256 * 35];                        // 35KB staging, stride 35
    int cnt = g_lvcnt[lvl];
    int t = threadIdx.x;
    if ((int)blockIdx.x >= cnt) return;
    ((ulonglong2*)Wsh)[t] = ((const ulonglong2*)(node_w + 1024))[t];
    const int* list = g_lvnodes + lvl * NN;
    int b = t;
    for (int ni = blockIdx.x; ni < cnt; ni += gridDim.x) {
        int node = list[ni];
        int c0 = g_off[node], c1 = g_off[node + 1];
        // phase 1: children sum in registers
        float4 a[8];
        #pragma unroll
        for (int q = 0; q < 8; q++) a[q] = make_float4(0.f, 0.f, 0.f, 0.f);
        for (int ci = c0; ci < c1; ci++) {
            int c = g_child[ci];
            const float4* src = g_h4 + (size_t)c * 2048 + b;
            #pragma unroll
            for (int q = 0; q < 8; q++) {
                float4 v = src[q * 256];
                a[q].x += v.x; a[q].y += v.y; a[q].z += v.z; a[q].w += v.w;
            }
        }
        // spill csum to smem (conflict-free: stride 35 -> bank 3t+k)
        const float* af = (const float*)a;
        #pragma unroll
        for (int k = 0; k < 32; k++) csum[t * 35 + k] = af[k];
        __syncthreads();   // covers Wsh visibility (first iter) + csum reuse across iters
        // pair-term init from global tables (L1-resident)
        int ta = g_tA[node * BB + b];
        int tb = g_tB[node * BB + b];
        const ulonglong2* pa = (const ulonglong2*)(g_Pa + ta * 32);
        const ulonglong2* pb = (const ulonglong2*)(g_Pb + tb * 32);
        unsigned long long o2[16];
        #pragma unroll
        for (int q = 0; q < 8; q++) {
            ulonglong2 x = pa[q], y = pb[q];
            o2[2 * q]     = add2(x.x, y.x);
            o2[2 * q + 1] = add2(x.y, y.y);
        }
        // matvec: o2[j] += csum[k] * W[32+k][j]
        #pragma unroll
        for (int kk = 0; kk < 32; kk++) {
            float s = csum[t * 35 + kk];
            unsigned long long a2 = pack2(s, s);
            const ulonglong2* wrow = (const ulonglong2*)(Wsh + kk * 16);
            #pragma unroll
            for (int j2 = 0; j2 < 8; j2++) {
                ulonglong2 w = wrow[j2];
                fma2(o2[2 * j2], a2, w.x);
                fma2(o2[2 * j2 + 1], a2, w.y);
            }
        }
        // relu + store
        float4* dst = g_h4 + (size_t)node * 2048 + b;
        #pragma unroll
        for (int q = 0; q < 8; q++) {
            float l0, h0, l1, h1;
            unpack2(o2[2 * q], l0, h0);
            unpack2(o2[2 * q + 1], l1, h1);
            dst[q * 256] = make_float4(fmaxf(l0, 0.f), fmaxf(h0, 0.f),
                                       fmaxf(l1, 0.f), fmaxf(h1, 0.f));
        }
        __syncthreads();   // protect csum before next iteration (rare: ni+740 case)
    }
}

// ============ root partial sums (64 blocks) ============
__global__ void __launch_bounds__(256) k_f1() {
    int b = threadIdx.x, s = blockIdx.x;
    float4 acc[8];
    #pragma unroll
    for (int q = 0; q < 8; q++) acc[q] = make_float4(0.f, 0.f, 0.f, 0.f);
    int c0 = g_off[0], c1 = g_off[1];
    for (int ci = c0 + s; ci < c1; ci += 64) {
        int c = g_child[ci];
        const float4* src = g_h4 + (size_t)c * 2048 + b;
        #pragma unroll
        for (int q = 0; q < 8; q++) {
            float4 v = src[q * 256];
            acc[q].x += v.x; acc[q].y += v.y; acc[q].z += v.z; acc[q].w += v.w;
        }
    }
    float4* dst = g_p4 + (size_t)s * 2048 + b;
    #pragma unroll
    for (int q = 0; q < 8; q++) dst[q * 256] = acc[q];
}

// ============ root finish (1 block) ============
__global__ void __launch_bounds__(256) k_f23(const float* __restrict__ node_w,
                                             float* __restrict__ out) {
    int b = threadIdx.x;
    float4 acc[8];
    #pragma unroll
    for (int q = 0; q < 8; q++) acc[q] = make_float4(0.f, 0.f, 0.f, 0.f);
    for (int s = 0; s < 64; s++) {
        const float4* src = g_p4 + (size_t)s * 2048 + b;
        #pragma unroll
        for (int q = 0; q < 8; q++) {
            float4 v = src[q * 256];
            acc[q].x += v.x; acc[q].y += v.y; acc[q].z += v.z; acc[q].w += v.w;
        }
    }
    int ta = g_tA[b];
    int tb = g_tB[b];
    unsigned long long o2[16];
    #pragma unroll
    for (int q = 0; q < 8; q++) {
        ulonglong2 x = ((const ulonglong2*)(g_Pa + ta * 32))[q];
        ulonglong2 y = ((const ulonglong2*)(g_Pb + tb * 32))[q];
        o2[2 * q]     = add2(x.x, y.x);
        o2[2 * q + 1] = add2(x.y, y.y);
    }
    const float* af = (const float*)acc;
    #pragma unroll
    for (int k = 0; k < 32; k++) {
        unsigned long long a2 = pack2(af[k], af[k]);
        const ulonglong2* wrow = (const ulonglong2*)(node_w + 1024 + k * 32);
        #pragma unroll
        for (int j2 = 0; j2 < 8; j2++) {
            ulonglong2 w = wrow[j2];
            fma2(o2[2 * j2], a2, w.x);
            fma2(o2[2 * j2 + 1], a2, w.y);
        }
    }
    float val = 0.f;
    #pragma unroll
    for (int q = 0; q < 8; q++) {
        float l0, h0, l1, h1;
        unpack2(o2[2 * q], l0, h0);
        unpack2(o2[2 * q + 1], l1, h1);
        val += fmaxf(l0, 0.f) * g_v[4 * q]     + fmaxf(h0, 0.f) * g_v[4 * q + 1]
             + fmaxf(l1, 0.f) * g_v[4 * q + 2] + fmaxf(h1, 0.f) * g_v[4 * q + 3];
    }
    out[b] = val + g_s;
}

// ---------------- launch ----------------
extern "C" void kernel_launch(void* const* d_in, const int* in_sizes, int n_in,
                              void* d_out, int out_size) {
    const int*   kind        = (const int*)d_in[0];
    const int*   height      = (const int*)d_in[1];
    const int*   parent      = (const int*)d_in[2];
    const int*   tok_a       = (const int*)d_in[3];
    const int*   tok_b       = (const int*)d_in[4];
    const int*   ptr_time    = (const int*)d_in[5];
    const float* first_notes = (const float*)d_in[6];
    const float* lstm_out    = (const float*)d_in[7];
    const float* embedding   = (const float*)d_in[8];
    const float* leaf_w1     = (const float*)d_in[9];
    const float* leaf_b1     = (const float*)d_in[10];
    const float* leaf_w2     = (const float*)d_in[11];
    const float* leaf_b2     = (const float*)d_in[12];
    const float* node_w      = (const float*)d_in[13];
    const float* node_b      = (const float*)d_in[14];
    const float* ptr_w       = (const float*)d_in[15];
    const float* ptr_b       = (const float*)d_in[16];
    const float* ff_w1       = (const float*)d_in[17];
    const float* ff_b1       = (const float*)d_in[18];
    const float* ff_w2       = (const float*)d_in[19];
    const float* ff_b2       = (const float*)d_in[20];
    const float* tail_w      = (const float*)d_in[21];
    const float* tail_b      = (const float*)d_in[22];
    float* out = (float*)d_out;

    k_prep<<<6177, 256>>>(parent, height, tok_a, tok_b, lstm_out, first_notes,
                          ptr_w, ptr_b,
                          leaf_w1, leaf_b1, leaf_w2, leaf_b2,
                          ff_w1, ff_b1, ff_w2, ff_b2, tail_w, tail_b,
                          embedding, node_w, node_b);
    k_init<<<LVG, 256>>>(kind, ptr_time);
    for (int lvl = 1; lvl <= 5; lvl++)
        k_level<<<LVG, 256>>>(node_w, lvl);
    k_f1<<<64, 256>>>();
    k_f23<<<1, 256>>>(node_w, out);
}

// round 9
// speedup vs baseline: 1.7361x; 1.2841x over previous
#include <cuda_runtime.h>
#include <cuda_fp16.h>

#define NN    4096
#define BB    256
#define VOC   200
#define TT    128
#define LVG   740

// ---------------- scratch (device globals; no allocation) ----------------
static __device__ float4 g_h4[(size_t)NN * 8 * BB];      // [node][q][b]
static __device__ float4 g_p4[64 * 8 * BB];              // root partials
static __device__ float g_Wl[32 * 32];
static __device__ float g_bl[32];
static __device__ float g_Pa[VOC * 32];                  // fp32 (root use)
static __device__ float g_Pb[VOC * 32];
static __device__ __align__(16) __half g_PaH[VOC * 32];  // fp16 gather tables
static __device__ __align__(16) __half g_PbH[VOC * 32];
static __device__ __align__(16) __half g_LaH[VOC * 32];
static __device__ __align__(16) __half g_LbH[VOC * 32];
static __device__ float g_F[BB * 32];
static __device__ float g_Lt[(size_t)BB * TT * 32];
static __device__ float g_v[32];
static __device__ float g_s;
static __device__ int   g_cnt[NN];
static __device__ int   g_cur[NN];
static __device__ int   g_off[NN + 1];
static __device__ int   g_child[NN];
static __device__ int   g_lvcnt[8];
static __device__ int   g_lvnodes[6 * NN];
static __device__ int   g_tA[NN * BB];
static __device__ int   g_tB[NN * BB];

// ---------------- f32x2 helpers ----------------
__device__ __forceinline__ unsigned long long pack2(float lo, float hi) {
    unsigned long long r;
    asm("mov.b64 %0, {%1, %2};" : "=l"(r) : "r"(__float_as_uint(lo)), "r"(__float_as_uint(hi)));
    return r;
}
__device__ __forceinline__ void unpack2(unsigned long long v, float& lo, float& hi) {
    unsigned int a, b;
    asm("mov.b64 {%0, %1}, %2;" : "=r"(a), "=r"(b) : "l"(v));
    lo = __uint_as_float(a);
    hi = __uint_as_float(b);
}
__device__ __forceinline__ void fma2(unsigned long long& d, unsigned long long a, unsigned long long b) {
    asm("fma.rn.f32x2 %0, %1, %2, %0;" : "+l"(d) : "l"(a), "l"(b));
}
__device__ __forceinline__ unsigned long long add2(unsigned long long a, unsigned long long b) {
    unsigned long long r;
    asm("add.rn.f32x2 %0, %1, %2;" : "=l"(r) : "l"(a), "l"(b));
    return r;
}

// gather two fp16 table rows, add, produce 16 packed f32x2
__device__ __forceinline__ void gather_pair_h(const __half* Pa, const __half* Pb,
                                              int ta, int tb, unsigned long long* o) {
    const uint4* A = (const uint4*)(Pa + ta * 32);
    const uint4* B = (const uint4*)(Pb + tb * 32);
    #pragma unroll
    for (int q = 0; q < 4; q++) {
        uint4 x = A[q], y = B[q];
        unsigned xs[4] = {x.x, x.y, x.z, x.w};
        unsigned ys[4] = {y.x, y.y, y.z, y.w};
        #pragma unroll
        for (int r = 0; r < 4; r++) {
            float2 fx = __half22float2(*(const __half2*)&xs[r]);
            float2 fy = __half22float2(*(const __half2*)&ys[r]);
            o[q * 4 + r] = pack2(fx.x + fy.x, fx.y + fy.y);
        }
    }
}

// ============ prep: transpose | Lt+F | CSR/scan/fuse/tables (role split) ============
__global__ void __launch_bounds__(256) k_prep(
    const int* __restrict__ parent, const int* __restrict__ height,
    const int* __restrict__ tok_a, const int* __restrict__ tok_b,
    const float* __restrict__ lstm, const float* __restrict__ fn,
    const float* __restrict__ pw, const float* __restrict__ pbias,
    const float* __restrict__ lw1, const float* __restrict__ lb1,
    const float* __restrict__ lw2, const float* __restrict__ lb2,
    const float* __restrict__ fw1, const float* __restrict__ fb1,
    const float* __restrict__ fw2, const float* __restrict__ fb2,
    const float* __restrict__ tw, const float* __restrict__ tb,
    const float* __restrict__ emb, const float* __restrict__ node_w,
    const float* __restrict__ node_b)
{
    int bid = blockIdx.x, t = threadIdx.x;
    if (bid < 2048) {
        __shared__ int tile[32][33];
        int arr = bid >> 10, tl = bid & 1023;
        int pt = tl >> 3, bt = tl & 7;
        const int* src = arr ? tok_b : tok_a;
        int* dst = arr ? g_tB : g_tA;
        int x = t & 31, y0 = t >> 5;
        #pragma unroll
        for (int y = y0; y < 32; y += 8)
            tile[y][x] = src[(size_t)(bt * 32 + y) * NN + pt * 32 + x];
        __syncthreads();
        #pragma unroll
        for (int y = y0; y < 32; y += 8)
            dst[(size_t)(pt * 32 + y) * BB + bt * 32 + x] = tile[x][y];
    } else if (bid < 6176) {
        int gid = (bid - 2048) * 256 + t;
        int r = gid >> 5, j = gid & 31;
        if (r < BB * TT) {
            const float* lr = lstm + (size_t)r * 64;
            float s = 0.f;
            #pragma unroll
            for (int k = 0; k < 64; k++)
                s += __ldg(lr + k) * __ldg(pw + (64 + k) * 32 + j);
            g_Lt[(size_t)r * 32 + j] = s;
        } else {
            int b = r - BB * TT;
            float s = pbias[j];
            #pragma unroll
            for (int k = 0; k < 64; k++)
                s += __ldg(fn + b * 64 + k) * __ldg(pw + k * 32 + j);
            g_F[b * 32 + j] = s;
        }
    } else {
        __shared__ int sc[256];
        __shared__ float u[32];
        __shared__ float Wlsh[1024];
        __shared__ float blsh[32];
        for (int i = t; i < NN; i += 256) { g_cnt[i] = 0; g_cur[i] = 0; }
        if (t < 8) g_lvcnt[t] = 0;
        __syncthreads();
        for (int c = t; c < NN; c += 256)
            if (c >= 1) atomicAdd(&g_cnt[parent[c]], 1);
        __syncthreads();
        int base = t * 16;
        int loc[16];
        int run = 0;
        #pragma unroll
        for (int r = 0; r < 16; r++) { loc[r] = run; run += g_cnt[base + r]; }
        sc[t] = run;
        __syncthreads();
        for (int off = 1; off < 256; off <<= 1) {
            int v = (t >= off) ? sc[t - off] : 0;
            __syncthreads();
            sc[t] += v;
            __syncthreads();
        }
        int excl = sc[t] - run;
        #pragma unroll
        for (int r = 0; r < 16; r++) g_off[base + r] = excl + loc[r];
        if (t == 255) g_off[NN] = sc[255];
        __syncthreads();
        for (int c = t; c < NN; c += 256) {
            if (c >= 1) {
                int p = parent[c];
                int pos = atomicAdd(&g_cur[p], 1);
                g_child[g_off[p] + pos] = c;
            }
            int h = height[c];
            if (h < 6) {
                int i = atomicAdd(&g_lvcnt[h], 1);
                g_lvnodes[h * NN + i] = c;
            }
        }
        // fused leaf weights
        for (int idx = t; idx < 1024; idx += 256) {
            int i = idx >> 5, j = idx & 31;
            float s = 0.f;
            for (int k = 0; k < 32; k++) s += lw1[i * 32 + k] * lw2[k * 32 + j];
            Wlsh[idx] = s;
        }
        if (t < 32) {
            float bsum = lb2[t];
            for (int k = 0; k < 32; k++) bsum += lb1[k] * lw2[k * 32 + t];
            blsh[t] = bsum;
            float uu = 0.f;
            for (int q = 0; q < 32; q++) uu += fw2[t * 32 + q] * tw[q];
            u[t] = uu;
        }
        __syncthreads();
        if (t < 32) {
            float vv = 0.f;
            for (int k = 0; k < 32; k++) vv += fw1[t * 32 + k] * u[k];
            g_v[t] = vv;
        }
        if (t == 0) {
            float ss = tb[0];
            for (int k = 0; k < 32; k++) ss += fb1[k] * u[k];
            for (int q = 0; q < 32; q++) ss += fb2[q] * tw[q];
            g_s = ss;
        }
        for (int idx = t; idx < VOC * 32; idx += 256) {
            int v = idx >> 5, jj = idx & 31;
            float la = blsh[jj], lb = 0.f, pa = node_b[jj], pb = 0.f;
            for (int e = 0; e < 16; e++) {
                float ev = emb[v * 16 + e];
                la += ev * Wlsh[e * 32 + jj];
                lb += ev * Wlsh[(16 + e) * 32 + jj];
                pa += ev * node_w[e * 32 + jj];
                pb += ev * node_w[(16 + e) * 32 + jj];
            }
            g_Pa[idx] = pa;
            g_Pb[idx] = pb;
            g_PaH[idx] = __float2half(pa);
            g_PbH[idx] = __float2half(pb);
            g_LaH[idx] = __float2half(la);
            g_LbH[idx] = __float2half(lb);
        }
    }
}

// ============ leaf init: fp16 table gathers ============
__global__ void __launch_bounds__(256, 4) k_init(const int* __restrict__ kind,
                                                 const int* __restrict__ ptr_time) {
    int cnt = g_lvcnt[0];
    int b = threadIdx.x;
    for (int ni = blockIdx.x; ni < cnt; ni += gridDim.x) {
        int node = g_lvnodes[ni];
        int kd = kind[node];
        float4 r[8];
        if (kd == 0) {
            int ta = g_tA[node * BB + b];
            int tb = g_tB[node * BB + b];
            unsigned long long o[16];
            gather_pair_h(g_LaH, g_LbH, ta, tb, o);
            #pragma unroll
            for (int q = 0; q < 8; q++) {
                float x0, x1, x2, x3;
                unpack2(o[2 * q], x0, x1);
                unpack2(o[2 * q + 1], x2, x3);
                r[q] = make_float4(x0, x1, x2, x3);
            }
        } else {
            int tm = ptr_time[(size_t)b * NN + node];
            const float4* A  = (const float4*)(g_F + b * 32);
            const float4* Bv = (const float4*)(g_Lt + ((size_t)b * TT + tm) * 32);
            #pragma unroll
            for (int q = 0; q < 8; q++) {
                float4 x = A[q], y = Bv[q];
                r[q] = make_float4(x.x + y.x, x.y + y.y, x.z + y.z, x.w + y.w);
            }
        }
        float4* dst = g_h4 + (size_t)node * 2048 + b;
        #pragma unroll
        for (int q = 0; q < 8; q++) dst[q * 256] = r[q];
    }
}

// ============ level: 128 threads/node, 2 b's per thread, fp16 gathers ============
__global__ void __launch_bounds__(128, 5) k_level(const float* __restrict__ node_w, int lvl) {
    __shared__ __align__(16) unsigned long long Wsh[512];   // 4KB bottom half of node_w
    __shared__ float csum[256 * 35];                        // 35.8KB
    int cnt = g_lvcnt[lvl];
    int t = threadIdx.x;
    if ((int)blockIdx.x >= cnt) return;
    ((ulonglong2*)Wsh)[t]       = ((const ulonglong2*)(node_w + 1024))[t];
    ((ulonglong2*)Wsh)[t + 128] = ((const ulonglong2*)(node_w + 1024))[t + 128];
    const int* list = g_lvnodes + lvl * NN;
    for (int ni = blockIdx.x; ni < cnt; ni += gridDim.x) {
        int node = list[ni];
        int c0 = g_off[node], c1 = g_off[node + 1];
        // phase 1: children sums for b=t and b=t+128, staged to smem
        #pragma unroll
        for (int hf = 0; hf < 2; hf++) {
            int b = t + hf * 128;
            float4 a[8];
            #pragma unroll
            for (int q = 0; q < 8; q++) a[q] = make_float4(0.f, 0.f, 0.f, 0.f);
            for (int ci = c0; ci < c1; ci++) {
                int c = g_child[ci];
                const float4* src = g_h4 + (size_t)c * 2048 + b;
                #pragma unroll
                for (int q = 0; q < 8; q++) {
                    float4 v = src[q * 256];
                    a[q].x += v.x; a[q].y += v.y; a[q].z += v.z; a[q].w += v.w;
                }
            }
            const float* af = (const float*)a;
            #pragma unroll
            for (int k = 0; k < 32; k++) csum[b * 35 + k] = af[k];
        }
        __syncthreads();
        // phase 2: pair gathers + dual matvec
        int b0 = t, b1 = t + 128;
        int ta0 = g_tA[node * BB + b0], tb0 = g_tB[node * BB + b0];
        int ta1 = g_tA[node * BB + b1], tb1 = g_tB[node * BB + b1];
        unsigned long long oA[16], oB[16];
        gather_pair_h(g_PaH, g_PbH, ta0, tb0, oA);
        gather_pair_h(g_PaH, g_PbH, ta1, tb1, oB);
        #pragma unroll
        for (int kk = 0; kk < 32; kk++) {
            float s0 = csum[b0 * 35 + kk];
            float s1 = csum[b1 * 35 + kk];
            unsigned long long a0 = pack2(s0, s0);
            unsigned long long a1 = pack2(s1, s1);
            const ulonglong2* wrow = (const ulonglong2*)(Wsh + kk * 16);
            #pragma unroll
            for (int j2 = 0; j2 < 8; j2++) {
                ulonglong2 w = wrow[j2];
                fma2(oA[2 * j2], a0, w.x);
                fma2(oA[2 * j2 + 1], a0, w.y);
                fma2(oB[2 * j2], a1, w.x);
                fma2(oB[2 * j2 + 1], a1, w.y);
            }
        }
        // relu + stores
        float4* d0 = g_h4 + (size_t)node * 2048 + b0;
        float4* d1 = g_h4 + (size_t)node * 2048 + b1;
        #pragma unroll
        for (int q = 0; q < 8; q++) {
            float l0, h0, l1, h1;
            unpack2(oA[2 * q], l0, h0);
            unpack2(oA[2 * q + 1], l1, h1);
            d0[q * 256] = make_float4(fmaxf(l0, 0.f), fmaxf(h0, 0.f),
                                      fmaxf(l1, 0.f), fmaxf(h1, 0.f));
            unpack2(oB[2 * q], l0, h0);
            unpack2(oB[2 * q + 1], l1, h1);
            d1[q * 256] = make_float4(fmaxf(l0, 0.f), fmaxf(h0, 0.f),
                                      fmaxf(l1, 0.f), fmaxf(h1, 0.f));
        }
        __syncthreads();
    }
}

// ============ root partial sums (64 blocks) ============
__global__ void __launch_bounds__(256) k_f1() {
    int b = threadIdx.x, s = blockIdx.x;
    float4 acc[8];
    #pragma unroll
    for (int q = 0; q < 8; q++) acc[q] = make_float4(0.f, 0.f, 0.f, 0.f);
    int c0 = g_off[0], c1 = g_off[1];
    for (int ci = c0 + s; ci < c1; ci += 64) {
        int c = g_child[ci];
        const float4* src = g_h4 + (size_t)c * 2048 + b;
        #pragma unroll
        for (int q = 0; q < 8; q++) {
            float4 v = src[q * 256];
            acc[q].x += v.x; acc[q].y += v.y; acc[q].z += v.z; acc[q].w += v.w;
        }
    }
    float4* dst = g_p4 + (size_t)s * 2048 + b;
    #pragma unroll
    for (int q = 0; q < 8; q++) dst[q * 256] = acc[q];
}

// ============ root finish (1 block) ============
__global__ void __launch_bounds__(256) k_f23(const float* __restrict__ node_w,
                                             float* __restrict__ out) {
    int b = threadIdx.x;
    float4 acc[8];
    #pragma unroll
    for (int q = 0; q < 8; q++) acc[q] = make_float4(0.f, 0.f, 0.f, 0.f);
    for (int s = 0; s < 64; s++) {
        const float4* src = g_p4 + (size_t)s * 2048 + b;
        #pragma unroll
        for (int q = 0; q < 8; q++) {
            float4 v = src[q * 256];
            acc[q].x += v.x; acc[q].y += v.y; acc[q].z += v.z; acc[q].w += v.w;
        }
    }
    int ta = g_tA[b];
    int tb = g_tB[b];
    unsigned long long o2[16];
    #pragma unroll
    for (int q = 0; q < 8; q++) {
        ulonglong2 x = ((const ulonglong2*)(g_Pa + ta * 32))[q];
        ulonglong2 y = ((const ulonglong2*)(g_Pb + tb * 32))[q];
        o2[2 * q]     = add2(x.x, y.x);
        o2[2 * q + 1] = add2(x.y, y.y);
    }
    const float* af = (const float*)acc;
    #pragma unroll
    for (int k = 0; k < 32; k++) {
        unsigned long long a2 = pack2(af[k], af[k]);
        const ulonglong2* wrow = (const ulonglong2*)(node_w + 1024 + k * 32);
        #pragma unroll
        for (int j2 = 0; j2 < 8; j2++) {
            ulonglong2 w = wrow[j2];
            fma2(o2[2 * j2], a2, w.x);
            fma2(o2[2 * j2 + 1], a2, w.y);
        }
    }
    float val = 0.f;
    #pragma unroll
    for (int q = 0; q < 8; q++) {
        float l0, h0, l1, h1;
        unpack2(o2[2 * q], l0, h0);
        unpack2(o2[2 * q + 1], l1, h1);
        val += fmaxf(l0, 0.f) * g_v[4 * q]     + fmaxf(h0, 0.f) * g_v[4 * q + 1]
             + fmaxf(l1, 0.f) * g_v[4 * q + 2] + fmaxf(h1, 0.f) * g_v[4 * q + 3];
    }
    out[b] = val + g_s;
}

// ---------------- launch ----------------
extern "C" void kernel_launch(void* const* d_in, const int* in_sizes, int n_in,
                              void* d_out, int out_size) {
    const int*   kind        = (const int*)d_in[0];
    const int*   height      = (const int*)d_in[1];
    const int*   parent      = (const int*)d_in[2];
    const int*   tok_a       = (const int*)d_in[3];
    const int*   tok_b       = (const int*)d_in[4];
    const int*   ptr_time    = (const int*)d_in[5];
    const float* first_notes = (const float*)d_in[6];
    const float* lstm_out    = (const float*)d_in[7];
    const float* embedding   = (const float*)d_in[8];
    const float* leaf_w1     = (const float*)d_in[9];
    const float* leaf_b1     = (const float*)d_in[10];
    const float* leaf_w2     = (const float*)d_in[11];
    const float* leaf_b2     = (const float*)d_in[12];
    const float* node_w      = (const float*)d_in[13];
    const float* node_b      = (const float*)d_in[14];
    const float* ptr_w       = (const float*)d_in[15];
    const float* ptr_b       = (const float*)d_in[16];
    const float* ff_w1       = (const float*)d_in[17];
    const float* ff_b1       = (const float*)d_in[18];
    const float* ff_w2       = (const float*)d_in[19];
    const float* ff_b2       = (const float*)d_in[20];
    const float* tail_w      = (const float*)d_in[21];
    const float* tail_b      = (const float*)d_in[22];
    float* out = (float*)d_out;

    k_prep<<<6177, 256>>>(parent, height, tok_a, tok_b, lstm_out, first_notes,
                          ptr_w, ptr_b,
                          leaf_w1, leaf_b1, leaf_w2, leaf_b2,
                          ff_w1, ff_b1, ff_w2, ff_b2, tail_w, tail_b,
                          embedding, node_w, node_b);
    k_init<<<LVG, 256>>>(kind, ptr_time);
    for (int lvl = 1; lvl <= 5; lvl++)
        k_level<<<LVG, 128>>>(node_w, lvl);
    k_f1<<<64, 256>>>();
    k_f23<<<1, 256>>>(node_w, out);
}